// round 6
// baseline (speedup 1.0000x reference)
#include <cuda_runtime.h>
#include <mma.h>
#include <math.h>

using namespace nvcuda;

#define N_NODES   50000
#define E_EDGES   1600000
#define EP        (E_EDGES + N_NODES)   // edges + self loops
#define NHEADS    4
#define HC        128
#define HC4       32                    // HC / 4
#define NGRAPH    64

#define PAD_A 36    // As row stride (floats)
#define PAD_B 132   // Bs row stride
#define PAD_C 132   // Cs row stride

// ---------------- scratch: float4-typed => guaranteed 16B alignment ------------
__device__ float4 g_h4[N_NODES * HC4];    // transformed features [N][32]x4
__device__ float4 g_agg4[N_NODES * HC4];  // aggregation output   [N][32]x4
__device__ float4 g_asrc4[N_NODES];       // per-node a_src, 4 heads
__device__ float4 g_adst4[N_NODES];       // per-node a_dst, 4 heads
__device__ int    g_deg[N_NODES];
__device__ int    g_rowptr[N_NODES + 1];
__device__ int    g_fill[N_NODES];
__device__ int    g_esrc[EP];             // src ids sorted by dst (CSR)
__device__ float  g_pool[NGRAPH * HC];
__device__ float  g_cnt[NGRAPH];

// ---------------- helpers ------------------------------------------------------
__device__ __forceinline__ float lrelu(float v) { return v > 0.f ? v : 0.2f * v; }
__device__ __forceinline__ float comp4(float4 v, int i) {
    return i == 0 ? v.x : (i == 1 ? v.y : (i == 2 ? v.z : v.w));
}
__device__ __forceinline__ int clampN(int v) {
    return v < 0 ? 0 : (v >= N_NODES ? N_NODES - 1 : v);
}

// ---------------- zero scratch --------------------------------------------------
__global__ void zero_deg_kernel() {
    int i = blockIdx.x * blockDim.x + threadIdx.x;
    if (i < N_NODES) g_deg[i] = 0;
}

__global__ void zero_pool_kernel() {
    int i = blockIdx.x * blockDim.x + threadIdx.x;
    if (i < NGRAPH * HC) g_pool[i] = 0.f;
    if (i < NGRAPH) g_cnt[i] = 0.f;
}

// ---------------- build CSR (counting sort by dst) -----------------------------
__global__ void hist_kernel(const int* __restrict__ ei) {
    int i = blockIdx.x * blockDim.x + threadIdx.x;
    if (i >= EP) return;
    int d = (i < E_EDGES) ? clampN(ei[E_EDGES + i]) : (i - E_EDGES);
    atomicAdd(&g_deg[d], 1);
}

// one-pass scan: thread-serial chunks + single 1024-wide block scan
#define SCAN_PER ((N_NODES + 1023) / 1024)    // 49
__global__ void scan_kernel() {
    __shared__ int buf[1024];
    int tid  = threadIdx.x;
    int base = tid * SCAN_PER;
    int lim  = min(base + SCAN_PER, N_NODES);
    int sum = 0;
    for (int i = base; i < lim; ++i) sum += g_deg[i];
    buf[tid] = sum;
    __syncthreads();
    for (int off = 1; off < 1024; off <<= 1) {
        int t = (tid >= off) ? buf[tid - off] : 0;
        __syncthreads();
        buf[tid] += t;
        __syncthreads();
    }
    int run = buf[tid] - sum;   // exclusive offset for this thread's chunk
    for (int i = base; i < lim; ++i) {
        g_rowptr[i] = run;
        g_fill[i]   = run;
        run += g_deg[i];
    }
    if (tid == 1023) g_rowptr[N_NODES] = buf[1023];
}

__global__ void fill_kernel(const int* __restrict__ ei) {
    int i = blockIdx.x * blockDim.x + threadIdx.x;
    if (i >= EP) return;
    int s, d;
    if (i < E_EDGES) { s = clampN(ei[i]); d = clampN(ei[E_EDGES + i]); }
    else             { s = i - E_EDGES; d = s; }
    int pos = atomicAdd(&g_fill[d], 1);
    if (pos >= 0 && pos < EP) g_esrc[pos] = s;
}

// ---------------- tf32 tensor-core GEMM + fused attention ----------------------
// g_h[M,128] = A[M,128] @ B[128,128]; also writes g_asrc4/g_adst4.
// Block tile 64x128 (M x N), 256 threads = 8 warps in 4x2 (wm x wn).
// Each warp: 16x64 via 4 wmma m16n16k8 accumulators.
struct SmemAB { float As[64][PAD_A]; float Bs[32][PAD_B]; };
union SmemU { SmemAB ab; float Cs[64][PAD_C]; };

__global__ void gemm_att_kernel(const float* __restrict__ Aext,
                                const float* __restrict__ B,
                                const float* __restrict__ att_src,
                                const float* __restrict__ att_dst,
                                int use_ext, int M) {
    __shared__ __align__(16) SmemU sh;
    const float* Ap = use_ext ? Aext : (const float*)g_agg4;
    int tid = threadIdx.x;
    int wid = tid >> 5;
    int wm = wid & 3;        // 0..3  (16-row m-tile)
    int wn = wid >> 2;       // 0..1  (64-col n-group)
    int bm0 = blockIdx.x * 64;

    wmma::fragment<wmma::accumulator, 16, 16, 8, float> acc[4];
#pragma unroll
    for (int j = 0; j < 4; ++j) wmma::fill_fragment(acc[j], 0.f);

    for (int kt = 0; kt < 4; ++kt) {
        // load A tile [64][32] -> As (row-major), zero-padded past M
#pragma unroll
        for (int t = 0; t < 8; ++t) {
            int id = tid + t * 256;        // 0..2047
            int r  = id >> 5;
            int c  = id & 31;
            int gr = bm0 + r;
            sh.ab.As[r][c] = (gr < M) ? Ap[gr * 128 + kt * 32 + c] : 0.f;
        }
        // load B tile [32][128] as float4
#pragma unroll
        for (int t = 0; t < 4; ++t) {
            int id  = tid + t * 256;       // 0..1023 float4 units
            int row = id >> 5;
            int c4  = id & 31;
            ((float4*)sh.ab.Bs[row])[c4] = ((const float4*)&B[(kt * 32 + row) * 128])[c4];
        }
        __syncthreads();
#pragma unroll
        for (int ks = 0; ks < 4; ++ks) {
            wmma::fragment<wmma::matrix_a, 16, 16, 8, wmma::precision::tf32, wmma::row_major> a;
            wmma::load_matrix_sync(a, &sh.ab.As[wm * 16][ks * 8], PAD_A);
#pragma unroll
            for (int i = 0; i < a.num_elements; ++i) a.x[i] = wmma::__float_to_tf32(a.x[i]);
#pragma unroll
            for (int j = 0; j < 4; ++j) {
                wmma::fragment<wmma::matrix_b, 16, 16, 8, wmma::precision::tf32, wmma::row_major> b;
                wmma::load_matrix_sync(b, &sh.ab.Bs[ks * 8][wn * 64 + j * 16], PAD_B);
#pragma unroll
                for (int i = 0; i < b.num_elements; ++i) b.x[i] = wmma::__float_to_tf32(b.x[i]);
                wmma::mma_sync(acc[j], a, b, acc[j]);
            }
        }
        __syncthreads();
    }

    // stage C tile in smem
#pragma unroll
    for (int j = 0; j < 4; ++j)
        wmma::store_matrix_sync(&sh.Cs[wm * 16][wn * 64 + j * 16], acc[j], PAD_C,
                                wmma::mem_row_major);
    __syncthreads();

    // fused attention: thread -> (row = tid>>2, head = tid&3)
    {
        int r  = tid >> 2;
        int hd = tid & 3;
        int gr = bm0 + r;
        if (gr < M) {
            float s = 0.f, d = 0.f;
#pragma unroll
            for (int i = 0; i < 32; ++i) {
                float v = sh.Cs[r][hd * 32 + i];
                s += v * att_src[hd * 32 + i];
                d += v * att_dst[hd * 32 + i];
            }
            ((float*)g_asrc4)[gr * 4 + hd] = s;
            ((float*)g_adst4)[gr * 4 + hd] = d;
        }
    }

    // write h (vectorized)
#pragma unroll
    for (int t = 0; t < 8; ++t) {
        int id  = tid + t * 256;   // 0..2047 float4 units
        int row = id >> 5;
        int c4  = id & 31;
        int gr  = bm0 + row;
        if (gr < M)
            g_h4[gr * HC4 + c4] = *(const float4*)&sh.Cs[row][c4 * 4];
    }
}

// ---------------- GAT aggregation: one warp per node, no atomics ---------------
// bias != nullptr : fused +bias and ELU on the output (layer 1).
__global__ void agg_kernel(const float* __restrict__ bias) {
    int w = (blockIdx.x * blockDim.x + threadIdx.x) >> 5;
    if (w >= N_NODES) return;
    int lane = threadIdx.x & 31;
    int n = w;
    int beg = g_rowptr[n];
    int end = g_rowptr[n + 1];
    float4 ad = g_adst4[n];

    // pass 1: per-head max over incoming edges
    float4 mx = make_float4(-1e30f, -1e30f, -1e30f, -1e30f);
    for (int j = beg + lane; j < end; j += 32) {
        int s = g_esrc[j];
        float4 as = g_asrc4[s];
        mx.x = fmaxf(mx.x, lrelu(as.x + ad.x));
        mx.y = fmaxf(mx.y, lrelu(as.y + ad.y));
        mx.z = fmaxf(mx.z, lrelu(as.z + ad.z));
        mx.w = fmaxf(mx.w, lrelu(as.w + ad.w));
    }
#pragma unroll
    for (int off = 16; off; off >>= 1) {
        mx.x = fmaxf(mx.x, __shfl_xor_sync(0xffffffffu, mx.x, off));
        mx.y = fmaxf(mx.y, __shfl_xor_sync(0xffffffffu, mx.y, off));
        mx.z = fmaxf(mx.z, __shfl_xor_sync(0xffffffffu, mx.z, off));
        mx.w = fmaxf(mx.w, __shfl_xor_sync(0xffffffffu, mx.w, off));
    }

    // pass 2: per-head denom
    float4 sm = make_float4(0.f, 0.f, 0.f, 0.f);
    for (int j = beg + lane; j < end; j += 32) {
        int s = g_esrc[j];
        float4 as = g_asrc4[s];
        sm.x += __expf(lrelu(as.x + ad.x) - mx.x);
        sm.y += __expf(lrelu(as.y + ad.y) - mx.y);
        sm.z += __expf(lrelu(as.z + ad.z) - mx.z);
        sm.w += __expf(lrelu(as.w + ad.w) - mx.w);
    }
#pragma unroll
    for (int off = 16; off; off >>= 1) {
        sm.x += __shfl_xor_sync(0xffffffffu, sm.x, off);
        sm.y += __shfl_xor_sync(0xffffffffu, sm.y, off);
        sm.z += __shfl_xor_sync(0xffffffffu, sm.z, off);
        sm.w += __shfl_xor_sync(0xffffffffu, sm.w, off);
    }
    float4 inv4 = make_float4(1.f / (sm.x + 1e-16f), 1.f / (sm.y + 1e-16f),
                              1.f / (sm.z + 1e-16f), 1.f / (sm.w + 1e-16f));

    // pass 3: accumulate messages. Each lane owns 4 output channels.
    int hd = lane >> 3;
    float4 acc = make_float4(0.f, 0.f, 0.f, 0.f);
    for (int j0 = beg; j0 < end; j0 += 8) {
        int je = j0 + (lane >> 2);
        float a_l = 0.f;
        int s_l = 0;
        if (je < end) {
            s_l = g_esrc[je];
            int hh = lane & 3;
            float e = lrelu(((const float*)&g_asrc4[s_l])[hh] + comp4(ad, hh));
            a_l = __expf(e - comp4(mx, hh)) * comp4(inv4, hh);
        }
        int cnt = min(8, end - j0);
        for (int t = 0; t < cnt; ++t) {
            float alpha = __shfl_sync(0xffffffffu, a_l, t * 4 + hd);
            int s       = __shfl_sync(0xffffffffu, s_l, t * 4);
            float4 hv = g_h4[s * HC4 + lane];
            acc.x += hv.x * alpha;
            acc.y += hv.y * alpha;
            acc.z += hv.z * alpha;
            acc.w += hv.w * alpha;
        }
    }
    if (bias) {
        float b0 = bias[lane * 4 + 0], b1 = bias[lane * 4 + 1];
        float b2 = bias[lane * 4 + 2], b3 = bias[lane * 4 + 3];
        float v;
        v = acc.x + b0; acc.x = v > 0.f ? v : (__expf(v) - 1.f);
        v = acc.y + b1; acc.y = v > 0.f ? v : (__expf(v) - 1.f);
        v = acc.z + b2; acc.z = v > 0.f ? v : (__expf(v) - 1.f);
        v = acc.w + b3; acc.w = v > 0.f ? v : (__expf(v) - 1.f);
    }
    g_agg4[n * HC4 + lane] = acc;
}

// ---------------- global mean pool (batch is sorted, int32) --------------------
__global__ void pool_kernel(const int* __restrict__ batch) {
    const float* feats = (const float*)g_agg4;
    int c  = threadIdx.x;                 // channel 0..127
    int n0 = blockIdx.x * 128;
    int n1 = min(n0 + 128, N_NODES);
    if (n0 >= N_NODES) return;
    float acc = 0.f;
    int curg = batch[n0] & (NGRAPH - 1);
    int cnt_local = 0;
    for (int n = n0; n < n1; ++n) {
        int g = batch[n] & (NGRAPH - 1);
        if (g != curg) {
            atomicAdd(&g_pool[curg * HC + c], acc);
            if (c == 0) atomicAdd(&g_cnt[curg], (float)cnt_local);
            acc = 0.f; cnt_local = 0; curg = g;
        }
        acc += feats[n * HC + c];
        cnt_local++;
    }
    atomicAdd(&g_pool[curg * HC + c], acc);
    if (c == 0) atomicAdd(&g_cnt[curg], (float)cnt_local);
}

// ---------------- FC + log_softmax ---------------------------------------------
__global__ void final_kernel(const float* __restrict__ fcW, const float* __restrict__ fcb,
                             const float* __restrict__ b2, float* __restrict__ out) {
    __shared__ float sh[128 * 8 + 8];
    int g = blockIdx.x;
    int c = threadIdx.x;      // 0..127
    float cnt = g_cnt[g];
    float mean = 0.f;
    if (cnt > 0.f) mean = g_pool[g * HC + c] / cnt + b2[c];
#pragma unroll
    for (int j = 0; j < 8; ++j) sh[c * 8 + j] = mean * fcW[c * 8 + j];
    __syncthreads();
    if (c < 8) {
        float s = fcb[c];
        for (int k = 0; k < 128; ++k) s += sh[k * 8 + c];
        sh[1024 + c] = s;
    }
    __syncthreads();
    if (c == 0) {
        float mx = sh[1024];
#pragma unroll
        for (int j = 1; j < 8; ++j) mx = fmaxf(mx, sh[1024 + j]);
        float se = 0.f;
#pragma unroll
        for (int j = 0; j < 8; ++j) se += __expf(sh[1024 + j] - mx);
        float lse = logf(se) + mx;
#pragma unroll
        for (int j = 0; j < 8; ++j) out[g * 8 + j] = sh[1024 + j] - lse;
    }
}

// ---------------- launch --------------------------------------------------------
extern "C" void kernel_launch(void* const* d_in, const int* in_sizes, int n_in,
                              void* d_out, int out_size) {
    const float* x        = (const float*)d_in[0];
    const int*   ei       = (const int*)d_in[1];      // int32 (JAX x64 off)
    const int*   batch    = (const int*)d_in[2];      // int32
    const float* W1       = (const float*)d_in[3];
    const float* att_src1 = (const float*)d_in[4];
    const float* att_dst1 = (const float*)d_in[5];
    const float* b1       = (const float*)d_in[6];
    const float* W2       = (const float*)d_in[7];
    const float* att_src2 = (const float*)d_in[8];
    const float* att_dst2 = (const float*)d_in[9];
    const float* b2       = (const float*)d_in[10];
    const float* fcW      = (const float*)d_in[11];
    const float* fcb      = (const float*)d_in[12];
    float*       out      = (float*)d_out;

    const int EB = (EP + 255) / 256;
    const int GB = (N_NODES + 63) / 64;

    // ---- build CSR (sorted by dst); reused by both layers ----
    zero_deg_kernel<<<(N_NODES + 255) / 256, 256>>>();
    hist_kernel<<<EB, 256>>>(ei);
    scan_kernel<<<1, 1024>>>();
    fill_kernel<<<EB, 256>>>(ei);

    // ---- layer 1 ----
    gemm_att_kernel<<<GB, 256>>>(x, W1, att_src1, att_dst1, 1, N_NODES);
    agg_kernel<<<(N_NODES + 7) / 8, 256>>>(b1);        // fused +b1, ELU

    // ---- layer 2 ----
    gemm_att_kernel<<<GB, 256>>>(nullptr, W2, att_src2, att_dst2, 0, N_NODES);
    agg_kernel<<<(N_NODES + 7) / 8, 256>>>(nullptr);

    // ---- pool + FC + log_softmax ----
    zero_pool_kernel<<<(NGRAPH * HC + 255) / 256, 256>>>();
    pool_kernel<<<(N_NODES + 127) / 128, 128>>>(batch);
    final_kernel<<<NGRAPH, 128>>>(fcW, fcb, b2, out);
}

// round 7
// speedup vs baseline: 1.0955x; 1.0955x over previous
#include <cuda_runtime.h>
#include <cuda_fp16.h>
#include <math.h>

#define N_NODES   50000
#define E_EDGES   1600000
#define EP        (E_EDGES + N_NODES)   // edges + self loops
#define NHEADS    4
#define HC        128
#define HC4       32                    // HC / 4
#define NGRAPH    64

// ---------------- scratch ------------------------------------------------------
__device__ uint2  g_h16[N_NODES * HC4];   // transformed features, fp16x4 per lane-slot
__device__ float4 g_agg4[N_NODES * HC4];  // aggregation output (fp32)
__device__ float4 g_asrc4[N_NODES];       // per-node a_src, 4 heads
__device__ float4 g_adst4[N_NODES];       // per-node a_dst, 4 heads
__device__ int    g_deg[N_NODES];
__device__ int    g_rowptr[N_NODES + 1];
__device__ int    g_fill[N_NODES];
__device__ int    g_esrc[EP];             // src ids sorted by dst (CSR)
__device__ float  g_pool[NGRAPH * HC];
__device__ float  g_cnt[NGRAPH];

// ---------------- helpers ------------------------------------------------------
__device__ __forceinline__ float lrelu(float v) { return v > 0.f ? v : 0.2f * v; }
__device__ __forceinline__ float comp4(float4 v, int i) {
    return i == 0 ? v.x : (i == 1 ? v.y : (i == 2 ? v.z : v.w));
}
__device__ __forceinline__ int clampN(int v) {
    return v < 0 ? 0 : (v >= N_NODES ? N_NODES - 1 : v);
}

// ---------------- zero scratch --------------------------------------------------
__global__ void zero_deg_kernel() {
    int i = blockIdx.x * blockDim.x + threadIdx.x;
    if (i < N_NODES) g_deg[i] = 0;
}

__global__ void zero_pool_kernel() {
    int i = blockIdx.x * blockDim.x + threadIdx.x;
    if (i < NGRAPH * HC) g_pool[i] = 0.f;
    if (i < NGRAPH) g_cnt[i] = 0.f;
}

// ---------------- build CSR (counting sort by dst) -----------------------------
__global__ void hist_kernel(const int* __restrict__ ei) {
    int i = blockIdx.x * blockDim.x + threadIdx.x;
    if (i >= EP) return;
    int d = (i < E_EDGES) ? clampN(ei[E_EDGES + i]) : (i - E_EDGES);
    atomicAdd(&g_deg[d], 1);
}

#define SCAN_PER ((N_NODES + 1023) / 1024)    // 49
__global__ void scan_kernel() {
    __shared__ int buf[1024];
    int tid  = threadIdx.x;
    int base = tid * SCAN_PER;
    int lim  = min(base + SCAN_PER, N_NODES);
    int sum = 0;
    for (int i = base; i < lim; ++i) sum += g_deg[i];
    buf[tid] = sum;
    __syncthreads();
    for (int off = 1; off < 1024; off <<= 1) {
        int t = (tid >= off) ? buf[tid - off] : 0;
        __syncthreads();
        buf[tid] += t;
        __syncthreads();
    }
    int run = buf[tid] - sum;
    for (int i = base; i < lim; ++i) {
        g_rowptr[i] = run;
        g_fill[i]   = run;
        run += g_deg[i];
    }
    if (tid == 1023) g_rowptr[N_NODES] = buf[1023];
}

__global__ void fill_kernel(const int* __restrict__ ei) {
    int i = blockIdx.x * blockDim.x + threadIdx.x;
    if (i >= EP) return;
    int s, d;
    if (i < E_EDGES) { s = clampN(ei[i]); d = clampN(ei[E_EDGES + i]); }
    else             { s = i - E_EDGES; d = s; }
    int pos = atomicAdd(&g_fill[d], 1);
    if (pos >= 0 && pos < EP) g_esrc[pos] = s;
}

// ---------------- SGEMM + fused attention, fp16 h output -----------------------
// h[M,128] = A[M,128] @ B[128,128]; writes g_h16 (fp16) + g_asrc4/g_adst4 (fp32).
__global__ void gemm_att_kernel(const float* __restrict__ Aext,
                                const float* __restrict__ B,
                                const float* __restrict__ att_src,
                                const float* __restrict__ att_dst,
                                int use_ext, int M) {
    __shared__ __align__(16) float As[32][68];     // [k][m]
    __shared__ __align__(16) float Bs[32][128];    // [k][n]
    const float* Ap = use_ext ? Aext : (const float*)g_agg4;
    int tid = threadIdx.x;
    int tr = tid >> 5;      // warp id 0..7 (row group)
    int tc = tid & 31;      // lane (col group)
    int bm0 = blockIdx.x * 64;
    int hd  = tc >> 3;
    int cin = (tc & 7) * 4;

    float4 acc[8];
#pragma unroll
    for (int i = 0; i < 8; ++i) acc[i] = make_float4(0.f, 0.f, 0.f, 0.f);

    for (int kt = 0; kt < 4; ++kt) {
#pragma unroll
        for (int t = 0; t < 8; ++t) {
            int id = tid + t * 256;
            int r  = id >> 5;
            int cc = id & 31;
            int gr = bm0 + r;
            As[cc][r] = (gr < M) ? Ap[gr * 128 + kt * 32 + cc] : 0.f;
        }
#pragma unroll
        for (int t = 0; t < 4; ++t) {
            int id  = tid + t * 256;
            int row = id >> 5;
            int c4  = id & 31;
            ((float4*)Bs[row])[c4] = ((const float4*)&B[(kt * 32 + row) * 128])[c4];
        }
        __syncthreads();
#pragma unroll
        for (int k = 0; k < 32; ++k) {
            float4 a0 = ((const float4*)As[k])[tr * 2];
            float4 a1 = ((const float4*)As[k])[tr * 2 + 1];
            float4 b  = ((const float4*)Bs[k])[tc];
            acc[0].x += a0.x * b.x; acc[0].y += a0.x * b.y; acc[0].z += a0.x * b.z; acc[0].w += a0.x * b.w;
            acc[1].x += a0.y * b.x; acc[1].y += a0.y * b.y; acc[1].z += a0.y * b.z; acc[1].w += a0.y * b.w;
            acc[2].x += a0.z * b.x; acc[2].y += a0.z * b.y; acc[2].z += a0.z * b.z; acc[2].w += a0.z * b.w;
            acc[3].x += a0.w * b.x; acc[3].y += a0.w * b.y; acc[3].z += a0.w * b.z; acc[3].w += a0.w * b.w;
            acc[4].x += a1.x * b.x; acc[4].y += a1.x * b.y; acc[4].z += a1.x * b.z; acc[4].w += a1.x * b.w;
            acc[5].x += a1.y * b.x; acc[5].y += a1.y * b.y; acc[5].z += a1.y * b.z; acc[5].w += a1.y * b.w;
            acc[6].x += a1.z * b.x; acc[6].y += a1.z * b.y; acc[6].z += a1.z * b.z; acc[6].w += a1.z * b.w;
            acc[7].x += a1.w * b.x; acc[7].y += a1.w * b.y; acc[7].z += a1.w * b.z; acc[7].w += a1.w * b.w;
        }
        __syncthreads();
    }

    float as0 = att_src[hd * 32 + cin + 0], ad0 = att_dst[hd * 32 + cin + 0];
    float as1 = att_src[hd * 32 + cin + 1], ad1 = att_dst[hd * 32 + cin + 1];
    float as2 = att_src[hd * 32 + cin + 2], ad2 = att_dst[hd * 32 + cin + 2];
    float as3 = att_src[hd * 32 + cin + 3], ad3 = att_dst[hd * 32 + cin + 3];

    float* asrc_f = (float*)g_asrc4;
    float* adst_f = (float*)g_adst4;
#pragma unroll
    for (int i = 0; i < 8; ++i) {
        int gr = bm0 + tr * 8 + i;
        float s = acc[i].x * as0 + acc[i].y * as1 + acc[i].z * as2 + acc[i].w * as3;
        float d = acc[i].x * ad0 + acc[i].y * ad1 + acc[i].z * ad2 + acc[i].w * ad3;
#pragma unroll
        for (int off = 4; off; off >>= 1) {
            s += __shfl_xor_sync(0xffffffffu, s, off);
            d += __shfl_xor_sync(0xffffffffu, d, off);
        }
        if (gr < M) {
            __half2 lo = __floats2half2_rn(acc[i].x, acc[i].y);
            __half2 hi = __floats2half2_rn(acc[i].z, acc[i].w);
            uint2 u;
            u.x = *(unsigned*)&lo;
            u.y = *(unsigned*)&hi;
            g_h16[gr * HC4 + tc] = u;
            if ((tc & 7) == 0) {
                asrc_f[gr * 4 + hd] = s;
                adst_f[gr * 4 + hd] = d;
            }
        }
    }
}

// ---------------- GAT aggregation: one warp per node, no atomics ---------------
// online softmax (single stats pass) + fp16 h gather, uniform esrc broadcast.
// bias != nullptr : fused +bias and ELU on the output (layer 1).
__global__ void agg_kernel(const float* __restrict__ bias) {
    int w = (blockIdx.x * blockDim.x + threadIdx.x) >> 5;
    if (w >= N_NODES) return;
    int lane = threadIdx.x & 31;
    int n = w;
    int beg = g_rowptr[n];
    int end = g_rowptr[n + 1];
    float4 ad = g_adst4[n];

    // pass 1: online (max, sum) per head
    float4 mx = make_float4(-1e30f, -1e30f, -1e30f, -1e30f);
    float4 sm = make_float4(0.f, 0.f, 0.f, 0.f);
    for (int j = beg + lane; j < end; j += 32) {
        int s = g_esrc[j];
        float4 as = g_asrc4[s];
        float e, nm;
        e = lrelu(as.x + ad.x); nm = fmaxf(mx.x, e); sm.x = sm.x * __expf(mx.x - nm) + __expf(e - nm); mx.x = nm;
        e = lrelu(as.y + ad.y); nm = fmaxf(mx.y, e); sm.y = sm.y * __expf(mx.y - nm) + __expf(e - nm); mx.y = nm;
        e = lrelu(as.z + ad.z); nm = fmaxf(mx.z, e); sm.z = sm.z * __expf(mx.z - nm) + __expf(e - nm); mx.z = nm;
        e = lrelu(as.w + ad.w); nm = fmaxf(mx.w, e); sm.w = sm.w * __expf(mx.w - nm) + __expf(e - nm); mx.w = nm;
    }
#pragma unroll
    for (int off = 16; off; off >>= 1) {
        float m2, s2, nm;
        m2 = __shfl_xor_sync(0xffffffffu, mx.x, off); s2 = __shfl_xor_sync(0xffffffffu, sm.x, off);
        nm = fmaxf(mx.x, m2); sm.x = sm.x * __expf(mx.x - nm) + s2 * __expf(m2 - nm); mx.x = nm;
        m2 = __shfl_xor_sync(0xffffffffu, mx.y, off); s2 = __shfl_xor_sync(0xffffffffu, sm.y, off);
        nm = fmaxf(mx.y, m2); sm.y = sm.y * __expf(mx.y - nm) + s2 * __expf(m2 - nm); mx.y = nm;
        m2 = __shfl_xor_sync(0xffffffffu, mx.z, off); s2 = __shfl_xor_sync(0xffffffffu, sm.z, off);
        nm = fmaxf(mx.z, m2); sm.z = sm.z * __expf(mx.z - nm) + s2 * __expf(m2 - nm); mx.z = nm;
        m2 = __shfl_xor_sync(0xffffffffu, mx.w, off); s2 = __shfl_xor_sync(0xffffffffu, sm.w, off);
        nm = fmaxf(mx.w, m2); sm.w = sm.w * __expf(mx.w - nm) + s2 * __expf(m2 - nm); mx.w = nm;
    }
    float4 inv4 = make_float4(1.f / (sm.x + 1e-16f), 1.f / (sm.y + 1e-16f),
                              1.f / (sm.z + 1e-16f), 1.f / (sm.w + 1e-16f));

    // pass 2: accumulate messages. Each lane owns 4 output channels (fp16 source).
    int hd = lane >> 3;
    float4 acc = make_float4(0.f, 0.f, 0.f, 0.f);
    for (int j0 = beg; j0 < end; j0 += 8) {
        int je = j0 + (lane >> 2);
        float a_l = 0.f;
        if (je < end) {
            int s_l = g_esrc[je];
            int hh = lane & 3;
            float e = lrelu(((const float*)&g_asrc4[s_l])[hh] + comp4(ad, hh));
            a_l = __expf(e - comp4(mx, hh)) * comp4(inv4, hh);
        }
        int cnt = min(8, end - j0);
#pragma unroll 8
        for (int t = 0; t < cnt; ++t) {
            float alpha = __shfl_sync(0xffffffffu, a_l, t * 4 + hd);
            int s = g_esrc[j0 + t];                    // uniform broadcast load
            uint2 u = g_h16[s * HC4 + lane];
            float2 f0 = __half22float2(*(__half2*)&u.x);
            float2 f1 = __half22float2(*(__half2*)&u.y);
            acc.x += f0.x * alpha;
            acc.y += f0.y * alpha;
            acc.z += f1.x * alpha;
            acc.w += f1.y * alpha;
        }
    }
    if (bias) {
        float b0 = bias[lane * 4 + 0], b1 = bias[lane * 4 + 1];
        float b2 = bias[lane * 4 + 2], b3 = bias[lane * 4 + 3];
        float v;
        v = acc.x + b0; acc.x = v > 0.f ? v : (__expf(v) - 1.f);
        v = acc.y + b1; acc.y = v > 0.f ? v : (__expf(v) - 1.f);
        v = acc.z + b2; acc.z = v > 0.f ? v : (__expf(v) - 1.f);
        v = acc.w + b3; acc.w = v > 0.f ? v : (__expf(v) - 1.f);
    }
    g_agg4[n * HC4 + lane] = acc;
}

// ---------------- global mean pool (batch is sorted, int32) --------------------
__global__ void pool_kernel(const int* __restrict__ batch) {
    const float* feats = (const float*)g_agg4;
    int c  = threadIdx.x;
    int n0 = blockIdx.x * 128;
    int n1 = min(n0 + 128, N_NODES);
    if (n0 >= N_NODES) return;
    float acc = 0.f;
    int curg = batch[n0] & (NGRAPH - 1);
    int cnt_local = 0;
    for (int n = n0; n < n1; ++n) {
        int g = batch[n] & (NGRAPH - 1);
        if (g != curg) {
            atomicAdd(&g_pool[curg * HC + c], acc);
            if (c == 0) atomicAdd(&g_cnt[curg], (float)cnt_local);
            acc = 0.f; cnt_local = 0; curg = g;
        }
        acc += feats[n * HC + c];
        cnt_local++;
    }
    atomicAdd(&g_pool[curg * HC + c], acc);
    if (c == 0) atomicAdd(&g_cnt[curg], (float)cnt_local);
}

// ---------------- FC + log_softmax ---------------------------------------------
__global__ void final_kernel(const float* __restrict__ fcW, const float* __restrict__ fcb,
                             const float* __restrict__ b2, float* __restrict__ out) {
    __shared__ float sh[128 * 8 + 8];
    int g = blockIdx.x;
    int c = threadIdx.x;
    float cnt = g_cnt[g];
    float mean = 0.f;
    if (cnt > 0.f) mean = g_pool[g * HC + c] / cnt + b2[c];
#pragma unroll
    for (int j = 0; j < 8; ++j) sh[c * 8 + j] = mean * fcW[c * 8 + j];
    __syncthreads();
    if (c < 8) {
        float s = fcb[c];
        for (int k = 0; k < 128; ++k) s += sh[k * 8 + c];
        sh[1024 + c] = s;
    }
    __syncthreads();
    if (c == 0) {
        float mx = sh[1024];
#pragma unroll
        for (int j = 1; j < 8; ++j) mx = fmaxf(mx, sh[1024 + j]);
        float se = 0.f;
#pragma unroll
        for (int j = 0; j < 8; ++j) se += __expf(sh[1024 + j] - mx);
        float lse = logf(se) + mx;
#pragma unroll
        for (int j = 0; j < 8; ++j) out[g * 8 + j] = sh[1024 + j] - lse;
    }
}

// ---------------- launch --------------------------------------------------------
extern "C" void kernel_launch(void* const* d_in, const int* in_sizes, int n_in,
                              void* d_out, int out_size) {
    const float* x        = (const float*)d_in[0];
    const int*   ei       = (const int*)d_in[1];
    const int*   batch    = (const int*)d_in[2];
    const float* W1       = (const float*)d_in[3];
    const float* att_src1 = (const float*)d_in[4];
    const float* att_dst1 = (const float*)d_in[5];
    const float* b1       = (const float*)d_in[6];
    const float* W2       = (const float*)d_in[7];
    const float* att_src2 = (const float*)d_in[8];
    const float* att_dst2 = (const float*)d_in[9];
    const float* b2       = (const float*)d_in[10];
    const float* fcW      = (const float*)d_in[11];
    const float* fcb      = (const float*)d_in[12];
    float*       out      = (float*)d_out;

    const int EB = (EP + 255) / 256;
    const int GB = (N_NODES + 63) / 64;

    zero_deg_kernel<<<(N_NODES + 255) / 256, 256>>>();
    hist_kernel<<<EB, 256>>>(ei);
    scan_kernel<<<1, 1024>>>();
    fill_kernel<<<EB, 256>>>(ei);

    gemm_att_kernel<<<GB, 256>>>(x, W1, att_src1, att_dst1, 1, N_NODES);
    agg_kernel<<<(N_NODES + 7) / 8, 256>>>(b1);

    gemm_att_kernel<<<GB, 256>>>(nullptr, W2, att_src2, att_dst2, 0, N_NODES);
    agg_kernel<<<(N_NODES + 7) / 8, 256>>>(nullptr);

    zero_pool_kernel<<<(NGRAPH * HC + 255) / 256, 256>>>();
    pool_kernel<<<(N_NODES + 127) / 128, 128>>>(batch);
    final_kernel<<<NGRAPH, 128>>>(fcW, fcb, b2, out);
}

// round 8
// speedup vs baseline: 1.1697x; 1.0677x over previous
#include <cuda_runtime.h>
#include <cuda_fp16.h>
#include <math.h>

#define N_NODES   50000
#define E_EDGES   1600000
#define E4        (E_EDGES / 4)         // 400000 int4 groups
#define EP        (E_EDGES + N_NODES)   // edges + self loops
#define NHEADS    4
#define HC        128
#define HC4       32
#define NGRAPH    64

// ---------------- scratch ------------------------------------------------------
__device__ uint2  g_h16[N_NODES * HC4];   // transformed features, fp16x4 per lane-slot
__device__ float4 g_agg4[N_NODES * HC4];  // aggregation output (fp32)
__device__ float4 g_asrc4[N_NODES];
__device__ float4 g_adst4[N_NODES];
__device__ int    g_deg[N_NODES];
__device__ int    g_rowptr[N_NODES + 1];
__device__ int    g_fill[N_NODES];
__device__ int    g_esrc[EP];             // src ids sorted by dst (CSR)
__device__ float  g_pool[NGRAPH * HC];
__device__ float  g_cnt[NGRAPH];

// ---------------- helpers ------------------------------------------------------
__device__ __forceinline__ float lrelu(float v) { return v > 0.f ? v : 0.2f * v; }
__device__ __forceinline__ float comp4(float4 v, int i) {
    return i == 0 ? v.x : (i == 1 ? v.y : (i == 2 ? v.z : v.w));
}
__device__ __forceinline__ int clampN(int v) {
    return v < 0 ? 0 : (v >= N_NODES ? N_NODES - 1 : v);
}

// ---------------- zero scratch --------------------------------------------------
__global__ void zero_deg_kernel() {
    int i = blockIdx.x * blockDim.x + threadIdx.x;
    if (i < N_NODES) g_deg[i] = 0;
}

__global__ void zero_pool_kernel() {
    int i = blockIdx.x * blockDim.x + threadIdx.x;
    if (i < NGRAPH * HC) g_pool[i] = 0.f;
    if (i < NGRAPH) g_cnt[i] = 0.f;
}

// ---------------- build CSR (counting sort by dst) -----------------------------
// real edges only, 4 per thread via int4 (self-loop degree folded into scan)
__global__ void hist_kernel(const int* __restrict__ ei) {
    int i = blockIdx.x * blockDim.x + threadIdx.x;
    if (i >= E4) return;
    int4 d4 = ((const int4*)(ei + E_EDGES))[i];
    atomicAdd(&g_deg[clampN(d4.x)], 1);
    atomicAdd(&g_deg[clampN(d4.y)], 1);
    atomicAdd(&g_deg[clampN(d4.z)], 1);
    atomicAdd(&g_deg[clampN(d4.w)], 1);
}

#define SCAN_PER ((N_NODES + 1023) / 1024)    // 49
__global__ void scan_kernel() {
    __shared__ int buf[1024];
    int tid  = threadIdx.x;
    int base = tid * SCAN_PER;
    int lim  = min(base + SCAN_PER, N_NODES);
    int sum = 0;
    for (int i = base; i < lim; ++i) sum += g_deg[i] + 1;   // +1 self loop
    buf[tid] = sum;
    __syncthreads();
    for (int off = 1; off < 1024; off <<= 1) {
        int t = (tid >= off) ? buf[tid - off] : 0;
        __syncthreads();
        buf[tid] += t;
        __syncthreads();
    }
    int run = buf[tid] - sum;
    for (int i = base; i < lim; ++i) {
        g_rowptr[i] = run;
        g_fill[i]   = run;
        run += g_deg[i] + 1;
    }
    if (tid == 1023) g_rowptr[N_NODES] = buf[1023];
}

// edges: 4 per thread (int4); tail threads write self loops
__global__ void fill_kernel(const int* __restrict__ ei) {
    int i = blockIdx.x * blockDim.x + threadIdx.x;
    if (i < E4) {
        int4 s4 = ((const int4*)ei)[i];
        int4 d4 = ((const int4*)(ei + E_EDGES))[i];
        int p;
        p = atomicAdd(&g_fill[clampN(d4.x)], 1); if (p >= 0 && p < EP) g_esrc[p] = clampN(s4.x);
        p = atomicAdd(&g_fill[clampN(d4.y)], 1); if (p >= 0 && p < EP) g_esrc[p] = clampN(s4.y);
        p = atomicAdd(&g_fill[clampN(d4.z)], 1); if (p >= 0 && p < EP) g_esrc[p] = clampN(s4.z);
        p = atomicAdd(&g_fill[clampN(d4.w)], 1); if (p >= 0 && p < EP) g_esrc[p] = clampN(s4.w);
    } else {
        int n = i - E4;
        if (n < N_NODES) {
            int p = atomicAdd(&g_fill[n], 1);
            if (p >= 0 && p < EP) g_esrc[p] = n;
        }
    }
}

// ---------------- SGEMM + fused attention, fp16 h output -----------------------
__global__ void gemm_att_kernel(const float* __restrict__ Aext,
                                const float* __restrict__ B,
                                const float* __restrict__ att_src,
                                const float* __restrict__ att_dst,
                                int use_ext, int M) {
    __shared__ __align__(16) float As[32][68];     // [k][m]
    __shared__ __align__(16) float Bs[32][128];    // [k][n]
    const float* Ap = use_ext ? Aext : (const float*)g_agg4;
    int tid = threadIdx.x;
    int tr = tid >> 5;
    int tc = tid & 31;
    int bm0 = blockIdx.x * 64;
    int hd  = tc >> 3;
    int cin = (tc & 7) * 4;

    float4 acc[8];
#pragma unroll
    for (int i = 0; i < 8; ++i) acc[i] = make_float4(0.f, 0.f, 0.f, 0.f);

    for (int kt = 0; kt < 4; ++kt) {
#pragma unroll
        for (int t = 0; t < 8; ++t) {
            int id = tid + t * 256;
            int r  = id >> 5;
            int cc = id & 31;
            int gr = bm0 + r;
            As[cc][r] = (gr < M) ? Ap[gr * 128 + kt * 32 + cc] : 0.f;
        }
#pragma unroll
        for (int t = 0; t < 4; ++t) {
            int id  = tid + t * 256;
            int row = id >> 5;
            int c4  = id & 31;
            ((float4*)Bs[row])[c4] = ((const float4*)&B[(kt * 32 + row) * 128])[c4];
        }
        __syncthreads();
#pragma unroll
        for (int k = 0; k < 32; ++k) {
            float4 a0 = ((const float4*)As[k])[tr * 2];
            float4 a1 = ((const float4*)As[k])[tr * 2 + 1];
            float4 b  = ((const float4*)Bs[k])[tc];
            acc[0].x += a0.x * b.x; acc[0].y += a0.x * b.y; acc[0].z += a0.x * b.z; acc[0].w += a0.x * b.w;
            acc[1].x += a0.y * b.x; acc[1].y += a0.y * b.y; acc[1].z += a0.y * b.z; acc[1].w += a0.y * b.w;
            acc[2].x += a0.z * b.x; acc[2].y += a0.z * b.y; acc[2].z += a0.z * b.z; acc[2].w += a0.z * b.w;
            acc[3].x += a0.w * b.x; acc[3].y += a0.w * b.y; acc[3].z += a0.w * b.z; acc[3].w += a0.w * b.w;
            acc[4].x += a1.x * b.x; acc[4].y += a1.x * b.y; acc[4].z += a1.x * b.z; acc[4].w += a1.x * b.w;
            acc[5].x += a1.y * b.x; acc[5].y += a1.y * b.y; acc[5].z += a1.y * b.z; acc[5].w += a1.y * b.w;
            acc[6].x += a1.z * b.x; acc[6].y += a1.z * b.y; acc[6].z += a1.z * b.z; acc[6].w += a1.z * b.w;
            acc[7].x += a1.w * b.x; acc[7].y += a1.w * b.y; acc[7].z += a1.w * b.z; acc[7].w += a1.w * b.w;
        }
        __syncthreads();
    }

    float as0 = att_src[hd * 32 + cin + 0], ad0 = att_dst[hd * 32 + cin + 0];
    float as1 = att_src[hd * 32 + cin + 1], ad1 = att_dst[hd * 32 + cin + 1];
    float as2 = att_src[hd * 32 + cin + 2], ad2 = att_dst[hd * 32 + cin + 2];
    float as3 = att_src[hd * 32 + cin + 3], ad3 = att_dst[hd * 32 + cin + 3];

    float* asrc_f = (float*)g_asrc4;
    float* adst_f = (float*)g_adst4;
#pragma unroll
    for (int i = 0; i < 8; ++i) {
        int gr = bm0 + tr * 8 + i;
        float s = acc[i].x * as0 + acc[i].y * as1 + acc[i].z * as2 + acc[i].w * as3;
        float d = acc[i].x * ad0 + acc[i].y * ad1 + acc[i].z * ad2 + acc[i].w * ad3;
#pragma unroll
        for (int off = 4; off; off >>= 1) {
            s += __shfl_xor_sync(0xffffffffu, s, off);
            d += __shfl_xor_sync(0xffffffffu, d, off);
        }
        if (gr < M) {
            __half2 lo = __floats2half2_rn(acc[i].x, acc[i].y);
            __half2 hi = __floats2half2_rn(acc[i].z, acc[i].w);
            uint2 u;
            u.x = *(unsigned*)&lo;
            u.y = *(unsigned*)&hi;
            g_h16[gr * HC4 + tc] = u;
            if ((tc & 7) == 0) {
                asrc_f[gr * 4 + hd] = s;
                adst_f[gr * 4 + hd] = d;
            }
        }
    }
}

// ---------------- GAT aggregation: warp/node, smem-staged 32-edge chunks -------
__global__ void agg_kernel(const float* __restrict__ bias) {
    __shared__ float4 s_alpha[8][32];
    __shared__ int    s_src[8][33];
    int wband = threadIdx.x >> 5;
    int w = (blockIdx.x * blockDim.x + threadIdx.x) >> 5;
    if (w >= N_NODES) return;
    int lane = threadIdx.x & 31;
    int beg = g_rowptr[w];
    int end = g_rowptr[w + 1];
    float4 ad = g_adst4[w];

    // pass 1: online (max, sum) per head
    float4 mx = make_float4(-1e30f, -1e30f, -1e30f, -1e30f);
    float4 sm = make_float4(0.f, 0.f, 0.f, 0.f);
    for (int j = beg + lane; j < end; j += 32) {
        int s = g_esrc[j];
        float4 as = g_asrc4[s];
        float e, nm;
        e = lrelu(as.x + ad.x); nm = fmaxf(mx.x, e); sm.x = sm.x * __expf(mx.x - nm) + __expf(e - nm); mx.x = nm;
        e = lrelu(as.y + ad.y); nm = fmaxf(mx.y, e); sm.y = sm.y * __expf(mx.y - nm) + __expf(e - nm); mx.y = nm;
        e = lrelu(as.z + ad.z); nm = fmaxf(mx.z, e); sm.z = sm.z * __expf(mx.z - nm) + __expf(e - nm); mx.z = nm;
        e = lrelu(as.w + ad.w); nm = fmaxf(mx.w, e); sm.w = sm.w * __expf(mx.w - nm) + __expf(e - nm); mx.w = nm;
    }
#pragma unroll
    for (int off = 16; off; off >>= 1) {
        float m2, s2, nm;
        m2 = __shfl_xor_sync(0xffffffffu, mx.x, off); s2 = __shfl_xor_sync(0xffffffffu, sm.x, off);
        nm = fmaxf(mx.x, m2); sm.x = sm.x * __expf(mx.x - nm) + s2 * __expf(m2 - nm); mx.x = nm;
        m2 = __shfl_xor_sync(0xffffffffu, mx.y, off); s2 = __shfl_xor_sync(0xffffffffu, sm.y, off);
        nm = fmaxf(mx.y, m2); sm.y = sm.y * __expf(mx.y - nm) + s2 * __expf(m2 - nm); mx.y = nm;
        m2 = __shfl_xor_sync(0xffffffffu, mx.z, off); s2 = __shfl_xor_sync(0xffffffffu, sm.z, off);
        nm = fmaxf(mx.z, m2); sm.z = sm.z * __expf(mx.z - nm) + s2 * __expf(m2 - nm); mx.z = nm;
        m2 = __shfl_xor_sync(0xffffffffu, mx.w, off); s2 = __shfl_xor_sync(0xffffffffu, sm.w, off);
        nm = fmaxf(mx.w, m2); sm.w = sm.w * __expf(mx.w - nm) + s2 * __expf(m2 - nm); mx.w = nm;
    }
    float4 inv4 = make_float4(1.f / (sm.x + 1e-16f), 1.f / (sm.y + 1e-16f),
                              1.f / (sm.z + 1e-16f), 1.f / (sm.w + 1e-16f));

    // pass 2: 32-edge chunks; alphas staged in smem; no shfl in hot loop
    int hd = lane >> 3;
    float4 acc = make_float4(0.f, 0.f, 0.f, 0.f);
    for (int j0 = beg; j0 < end; j0 += 32) {
        int je = j0 + lane;
        int cnt = min(32, end - j0);
        if (je < end) {
            int s_l = g_esrc[je];
            float4 as = g_asrc4[s_l];
            float4 al;
            al.x = __expf(lrelu(as.x + ad.x) - mx.x) * inv4.x;
            al.y = __expf(lrelu(as.y + ad.y) - mx.y) * inv4.y;
            al.z = __expf(lrelu(as.z + ad.z) - mx.z) * inv4.z;
            al.w = __expf(lrelu(as.w + ad.w) - mx.w) * inv4.w;
            s_alpha[wband][lane] = al;
            s_src[wband][lane]   = s_l;
        }
        __syncwarp();
#pragma unroll 4
        for (int t = 0; t < cnt; ++t) {
            float alpha = ((const float*)&s_alpha[wband][t])[hd];
            int s = s_src[wband][t];
            uint2 u = g_h16[s * HC4 + lane];
            float2 f0 = __half22float2(*(__half2*)&u.x);
            float2 f1 = __half22float2(*(__half2*)&u.y);
            acc.x += f0.x * alpha;
            acc.y += f0.y * alpha;
            acc.z += f1.x * alpha;
            acc.w += f1.y * alpha;
        }
        __syncwarp();
    }
    if (bias) {
        float b0 = bias[lane * 4 + 0], b1 = bias[lane * 4 + 1];
        float b2 = bias[lane * 4 + 2], b3 = bias[lane * 4 + 3];
        float v;
        v = acc.x + b0; acc.x = v > 0.f ? v : (__expf(v) - 1.f);
        v = acc.y + b1; acc.y = v > 0.f ? v : (__expf(v) - 1.f);
        v = acc.z + b2; acc.z = v > 0.f ? v : (__expf(v) - 1.f);
        v = acc.w + b3; acc.w = v > 0.f ? v : (__expf(v) - 1.f);
    }
    g_agg4[w * HC4 + lane] = acc;
}

// ---------------- global mean pool (batch is sorted, int32) --------------------
__global__ void pool_kernel(const int* __restrict__ batch) {
    const float* feats = (const float*)g_agg4;
    int c  = threadIdx.x;
    int n0 = blockIdx.x * 128;
    int n1 = min(n0 + 128, N_NODES);
    if (n0 >= N_NODES) return;
    float acc = 0.f;
    int curg = batch[n0] & (NGRAPH - 1);
    int cnt_local = 0;
    for (int n = n0; n < n1; ++n) {
        int g = batch[n] & (NGRAPH - 1);
        if (g != curg) {
            atomicAdd(&g_pool[curg * HC + c], acc);
            if (c == 0) atomicAdd(&g_cnt[curg], (float)cnt_local);
            acc = 0.f; cnt_local = 0; curg = g;
        }
        acc += feats[n * HC + c];
        cnt_local++;
    }
    atomicAdd(&g_pool[curg * HC + c], acc);
    if (c == 0) atomicAdd(&g_cnt[curg], (float)cnt_local);
}

// ---------------- FC + log_softmax ---------------------------------------------
__global__ void final_kernel(const float* __restrict__ fcW, const float* __restrict__ fcb,
                             const float* __restrict__ b2, float* __restrict__ out) {
    __shared__ float sh[128 * 8 + 8];
    int g = blockIdx.x;
    int c = threadIdx.x;
    float cnt = g_cnt[g];
    float mean = 0.f;
    if (cnt > 0.f) mean = g_pool[g * HC + c] / cnt + b2[c];
#pragma unroll
    for (int j = 0; j < 8; ++j) sh[c * 8 + j] = mean * fcW[c * 8 + j];
    __syncthreads();
    if (c < 8) {
        float s = fcb[c];
        for (int k = 0; k < 128; ++k) s += sh[k * 8 + c];
        sh[1024 + c] = s;
    }
    __syncthreads();
    if (c == 0) {
        float mx = sh[1024];
#pragma unroll
        for (int j = 1; j < 8; ++j) mx = fmaxf(mx, sh[1024 + j]);
        float se = 0.f;
#pragma unroll
        for (int j = 0; j < 8; ++j) se += __expf(sh[1024 + j] - mx);
        float lse = logf(se) + mx;
#pragma unroll
        for (int j = 0; j < 8; ++j) out[g * 8 + j] = sh[1024 + j] - lse;
    }
}

// ---------------- launch --------------------------------------------------------
extern "C" void kernel_launch(void* const* d_in, const int* in_sizes, int n_in,
                              void* d_out, int out_size) {
    const float* x        = (const float*)d_in[0];
    const int*   ei       = (const int*)d_in[1];
    const int*   batch    = (const int*)d_in[2];
    const float* W1       = (const float*)d_in[3];
    const float* att_src1 = (const float*)d_in[4];
    const float* att_dst1 = (const float*)d_in[5];
    const float* b1       = (const float*)d_in[6];
    const float* W2       = (const float*)d_in[7];
    const float* att_src2 = (const float*)d_in[8];
    const float* att_dst2 = (const float*)d_in[9];
    const float* b2       = (const float*)d_in[10];
    const float* fcW      = (const float*)d_in[11];
    const float* fcb      = (const float*)d_in[12];
    float*       out      = (float*)d_out;

    const int GB = (N_NODES + 63) / 64;
    const int FB = (E4 + N_NODES + 255) / 256;

    zero_deg_kernel<<<(N_NODES + 255) / 256, 256>>>();
    hist_kernel<<<(E4 + 255) / 256, 256>>>(ei);
    scan_kernel<<<1, 1024>>>();
    // launch index 3 == gemm1 (ncu -s profiles this slot)
    gemm_att_kernel<<<GB, 256>>>(x, W1, att_src1, att_dst1, 1, N_NODES);
    fill_kernel<<<FB, 256>>>(ei);
    agg_kernel<<<(N_NODES + 7) / 8, 256>>>(b1);

    gemm_att_kernel<<<GB, 256>>>(nullptr, W2, att_src2, att_dst2, 0, N_NODES);
    agg_kernel<<<(N_NODES + 7) / 8, 256>>>(nullptr);

    zero_pool_kernel<<<(NGRAPH * HC + 255) / 256, 256>>>();
    pool_kernel<<<(N_NODES + 127) / 128, 128>>>(batch);
    final_kernel<<<NGRAPH, 128>>>(fcW, fcb, b2, out);
}

// round 9
// speedup vs baseline: 1.2689x; 1.0848x over previous
#include <cuda_runtime.h>
#include <cuda_fp16.h>
#include <math.h>

#define N_NODES   50000
#define E_EDGES   1600000
#define E4        (E_EDGES / 4)
#define EP        (E_EDGES + N_NODES)
#define NHEADS    4
#define HC        128
#define HC4       32
#define NGRAPH    64

// ---------------- scratch ------------------------------------------------------
__device__ uint2  g_h16[N_NODES * HC4];   // transformed features, fp16x4 per lane-slot
__device__ float4 g_agg4[N_NODES * HC4];  // aggregation output (fp32)
__device__ float4 g_asrc4[N_NODES];
__device__ float4 g_adst4[N_NODES];
__device__ int    g_deg[N_NODES];
__device__ int    g_rowptr[N_NODES + 1];
__device__ int    g_fill[N_NODES];
__device__ int    g_esrc[EP];
__device__ float  g_pool[NGRAPH * HC];
__device__ float  g_cnt[NGRAPH];

// ---------------- helpers ------------------------------------------------------
__device__ __forceinline__ float lrelu(float v) { return v > 0.f ? v : 0.2f * v; }
__device__ __forceinline__ float comp4(float4 v, int i) {
    return i == 0 ? v.x : (i == 1 ? v.y : (i == 2 ? v.z : v.w));
}
__device__ __forceinline__ int clampN(int v) {
    return v < 0 ? 0 : (v >= N_NODES ? N_NODES - 1 : v);
}

// ---------------- zero scratch --------------------------------------------------
__global__ void zero_deg_kernel() {
    int i = blockIdx.x * blockDim.x + threadIdx.x;
    if (i < N_NODES) g_deg[i] = 0;
}

__global__ void zero_pool_kernel() {
    int i = blockIdx.x * blockDim.x + threadIdx.x;
    if (i < NGRAPH * HC) g_pool[i] = 0.f;
    if (i < NGRAPH) g_cnt[i] = 0.f;
}

// ---------------- build CSR (counting sort by dst) -----------------------------
__global__ void hist_kernel(const int* __restrict__ ei) {
    int i = blockIdx.x * blockDim.x + threadIdx.x;
    if (i >= E4) return;
    int4 d4 = ((const int4*)(ei + E_EDGES))[i];
    atomicAdd(&g_deg[clampN(d4.x)], 1);
    atomicAdd(&g_deg[clampN(d4.y)], 1);
    atomicAdd(&g_deg[clampN(d4.z)], 1);
    atomicAdd(&g_deg[clampN(d4.w)], 1);
}

#define SCAN_PER ((N_NODES + 1023) / 1024)    // 49
__global__ void scan_kernel() {
    __shared__ int buf[1024];
    int tid  = threadIdx.x;
    int base = tid * SCAN_PER;
    int lim  = min(base + SCAN_PER, N_NODES);
    int sum = 0;
    for (int i = base; i < lim; ++i) sum += g_deg[i] + 1;   // +1 self loop
    buf[tid] = sum;
    __syncthreads();
    for (int off = 1; off < 1024; off <<= 1) {
        int t = (tid >= off) ? buf[tid - off] : 0;
        __syncthreads();
        buf[tid] += t;
        __syncthreads();
    }
    int run = buf[tid] - sum;
    for (int i = base; i < lim; ++i) {
        g_rowptr[i] = run;
        g_fill[i]   = run;
        run += g_deg[i] + 1;
    }
    if (tid == 1023) g_rowptr[N_NODES] = buf[1023];
}

__global__ void fill_kernel(const int* __restrict__ ei) {
    int i = blockIdx.x * blockDim.x + threadIdx.x;
    if (i < E4) {
        int4 s4 = ((const int4*)ei)[i];
        int4 d4 = ((const int4*)(ei + E_EDGES))[i];
        int p;
        p = atomicAdd(&g_fill[clampN(d4.x)], 1); if (p >= 0 && p < EP) g_esrc[p] = clampN(s4.x);
        p = atomicAdd(&g_fill[clampN(d4.y)], 1); if (p >= 0 && p < EP) g_esrc[p] = clampN(s4.y);
        p = atomicAdd(&g_fill[clampN(d4.z)], 1); if (p >= 0 && p < EP) g_esrc[p] = clampN(s4.z);
        p = atomicAdd(&g_fill[clampN(d4.w)], 1); if (p >= 0 && p < EP) g_esrc[p] = clampN(s4.w);
    } else {
        int n = i - E4;
        if (n < N_NODES) {
            int p = atomicAdd(&g_fill[n], 1);
            if (p >= 0 && p < EP) g_esrc[p] = n;
        }
    }
}

// ---------------- SGEMM + fused attention, fp16 h output -----------------------
__global__ void gemm_att_kernel(const float* __restrict__ Aext,
                                const float* __restrict__ B,
                                const float* __restrict__ att_src,
                                const float* __restrict__ att_dst,
                                int use_ext, int M) {
    __shared__ __align__(16) float As[32][68];
    __shared__ __align__(16) float Bs[32][128];
    const float* Ap = use_ext ? Aext : (const float*)g_agg4;
    int tid = threadIdx.x;
    int tr = tid >> 5;
    int tc = tid & 31;
    int bm0 = blockIdx.x * 64;
    int hd  = tc >> 3;
    int cin = (tc & 7) * 4;

    float4 acc[8];
#pragma unroll
    for (int i = 0; i < 8; ++i) acc[i] = make_float4(0.f, 0.f, 0.f, 0.f);

    for (int kt = 0; kt < 4; ++kt) {
#pragma unroll
        for (int t = 0; t < 8; ++t) {
            int id = tid + t * 256;
            int r  = id >> 5;
            int cc = id & 31;
            int gr = bm0 + r;
            As[cc][r] = (gr < M) ? Ap[gr * 128 + kt * 32 + cc] : 0.f;
        }
#pragma unroll
        for (int t = 0; t < 4; ++t) {
            int id  = tid + t * 256;
            int row = id >> 5;
            int c4  = id & 31;
            ((float4*)Bs[row])[c4] = ((const float4*)&B[(kt * 32 + row) * 128])[c4];
        }
        __syncthreads();
#pragma unroll
        for (int k = 0; k < 32; ++k) {
            float4 a0 = ((const float4*)As[k])[tr * 2];
            float4 a1 = ((const float4*)As[k])[tr * 2 + 1];
            float4 b  = ((const float4*)Bs[k])[tc];
            acc[0].x += a0.x * b.x; acc[0].y += a0.x * b.y; acc[0].z += a0.x * b.z; acc[0].w += a0.x * b.w;
            acc[1].x += a0.y * b.x; acc[1].y += a0.y * b.y; acc[1].z += a0.y * b.z; acc[1].w += a0.y * b.w;
            acc[2].x += a0.z * b.x; acc[2].y += a0.z * b.y; acc[2].z += a0.z * b.z; acc[2].w += a0.z * b.w;
            acc[3].x += a0.w * b.x; acc[3].y += a0.w * b.y; acc[3].z += a0.w * b.z; acc[3].w += a0.w * b.w;
            acc[4].x += a1.x * b.x; acc[4].y += a1.x * b.y; acc[4].z += a1.x * b.z; acc[4].w += a1.x * b.w;
            acc[5].x += a1.y * b.x; acc[5].y += a1.y * b.y; acc[5].z += a1.y * b.z; acc[5].w += a1.y * b.w;
            acc[6].x += a1.z * b.x; acc[6].y += a1.z * b.y; acc[6].z += a1.z * b.z; acc[6].w += a1.z * b.w;
            acc[7].x += a1.w * b.x; acc[7].y += a1.w * b.y; acc[7].z += a1.w * b.z; acc[7].w += a1.w * b.w;
        }
        __syncthreads();
    }

    float as0 = att_src[hd * 32 + cin + 0], ad0 = att_dst[hd * 32 + cin + 0];
    float as1 = att_src[hd * 32 + cin + 1], ad1 = att_dst[hd * 32 + cin + 1];
    float as2 = att_src[hd * 32 + cin + 2], ad2 = att_dst[hd * 32 + cin + 2];
    float as3 = att_src[hd * 32 + cin + 3], ad3 = att_dst[hd * 32 + cin + 3];

    float* asrc_f = (float*)g_asrc4;
    float* adst_f = (float*)g_adst4;
#pragma unroll
    for (int i = 0; i < 8; ++i) {
        int gr = bm0 + tr * 8 + i;
        float s = acc[i].x * as0 + acc[i].y * as1 + acc[i].z * as2 + acc[i].w * as3;
        float d = acc[i].x * ad0 + acc[i].y * ad1 + acc[i].z * ad2 + acc[i].w * ad3;
#pragma unroll
        for (int off = 4; off; off >>= 1) {
            s += __shfl_xor_sync(0xffffffffu, s, off);
            d += __shfl_xor_sync(0xffffffffu, d, off);
        }
        if (gr < M) {
            __half2 lo = __floats2half2_rn(acc[i].x, acc[i].y);
            __half2 hi = __floats2half2_rn(acc[i].z, acc[i].w);
            uint2 u;
            u.x = *(unsigned*)&lo;
            u.y = *(unsigned*)&hi;
            g_h16[gr * HC4 + tc] = u;
            if ((tc & 7) == 0) {
                asrc_f[gr * 4 + hd] = s;
                adst_f[gr * 4 + hd] = d;
            }
        }
    }
}

// ---------------- GAT aggregation: single pass, no max subtraction -------------
// softmax(e) is shift-invariant; |e| is O(1) here so exp(e) cannot overflow.
// acc = sum_j exp(e_j) * h_j ; den = sum_j exp(e_j) ; out = acc / den.
__global__ void agg_kernel(const float* __restrict__ bias) {
    __shared__ float4 s_alpha[8][32];
    __shared__ int    s_src[8][33];
    int wband = threadIdx.x >> 5;
    int w = (blockIdx.x * blockDim.x + threadIdx.x) >> 5;
    if (w >= N_NODES) return;
    int lane = threadIdx.x & 31;
    int beg = g_rowptr[w];
    int end = g_rowptr[w + 1];
    float4 ad = g_adst4[w];

    int hd = lane >> 3;
    float4 acc  = make_float4(0.f, 0.f, 0.f, 0.f);
    float4 den  = make_float4(0.f, 0.f, 0.f, 0.f);

    for (int j0 = beg; j0 < end; j0 += 32) {
        int je = j0 + lane;
        int cnt = min(32, end - j0);
        if (je < end) {
            int s_l = g_esrc[je];
            float4 as = g_asrc4[s_l];
            float4 ex;
            ex.x = __expf(lrelu(as.x + ad.x));
            ex.y = __expf(lrelu(as.y + ad.y));
            ex.z = __expf(lrelu(as.z + ad.z));
            ex.w = __expf(lrelu(as.w + ad.w));
            den.x += ex.x; den.y += ex.y; den.z += ex.z; den.w += ex.w;
            s_alpha[wband][lane] = ex;
            s_src[wband][lane]   = s_l;
        }
        __syncwarp();
#pragma unroll 8
        for (int t = 0; t < cnt; ++t) {
            float wgt = ((const float*)&s_alpha[wband][t])[hd];
            int s = s_src[wband][t];
            uint2 u = g_h16[s * HC4 + lane];
            float2 f0 = __half22float2(*(__half2*)&u.x);
            float2 f1 = __half22float2(*(__half2*)&u.y);
            acc.x += f0.x * wgt;
            acc.y += f0.y * wgt;
            acc.z += f1.x * wgt;
            acc.w += f1.y * wgt;
        }
        __syncwarp();
    }

    // reduce per-head denominators across lanes
#pragma unroll
    for (int off = 16; off; off >>= 1) {
        den.x += __shfl_xor_sync(0xffffffffu, den.x, off);
        den.y += __shfl_xor_sync(0xffffffffu, den.y, off);
        den.z += __shfl_xor_sync(0xffffffffu, den.z, off);
        den.w += __shfl_xor_sync(0xffffffffu, den.w, off);
    }
    float inv = 1.f / (comp4(den, hd) + 1e-16f);
    acc.x *= inv; acc.y *= inv; acc.z *= inv; acc.w *= inv;

    if (bias) {
        float b0 = bias[lane * 4 + 0], b1 = bias[lane * 4 + 1];
        float b2 = bias[lane * 4 + 2], b3 = bias[lane * 4 + 3];
        float v;
        v = acc.x + b0; acc.x = v > 0.f ? v : (__expf(v) - 1.f);
        v = acc.y + b1; acc.y = v > 0.f ? v : (__expf(v) - 1.f);
        v = acc.z + b2; acc.z = v > 0.f ? v : (__expf(v) - 1.f);
        v = acc.w + b3; acc.w = v > 0.f ? v : (__expf(v) - 1.f);
    }
    g_agg4[w * HC4 + lane] = acc;
}

// ---------------- global mean pool (batch is sorted, int32) --------------------
__global__ void pool_kernel(const int* __restrict__ batch) {
    const float* feats = (const float*)g_agg4;
    int c  = threadIdx.x;
    int n0 = blockIdx.x * 128;
    int n1 = min(n0 + 128, N_NODES);
    if (n0 >= N_NODES) return;
    float acc = 0.f;
    int curg = batch[n0] & (NGRAPH - 1);
    int cnt_local = 0;
    for (int n = n0; n < n1; ++n) {
        int g = batch[n] & (NGRAPH - 1);
        if (g != curg) {
            atomicAdd(&g_pool[curg * HC + c], acc);
            if (c == 0) atomicAdd(&g_cnt[curg], (float)cnt_local);
            acc = 0.f; cnt_local = 0; curg = g;
        }
        acc += feats[n * HC + c];
        cnt_local++;
    }
    atomicAdd(&g_pool[curg * HC + c], acc);
    if (c == 0) atomicAdd(&g_cnt[curg], (float)cnt_local);
}

// ---------------- FC + log_softmax ---------------------------------------------
__global__ void final_kernel(const float* __restrict__ fcW, const float* __restrict__ fcb,
                             const float* __restrict__ b2, float* __restrict__ out) {
    __shared__ float sh[128 * 8 + 8];
    int g = blockIdx.x;
    int c = threadIdx.x;
    float cnt = g_cnt[g];
    float mean = 0.f;
    if (cnt > 0.f) mean = g_pool[g * HC + c] / cnt + b2[c];
#pragma unroll
    for (int j = 0; j < 8; ++j) sh[c * 8 + j] = mean * fcW[c * 8 + j];
    __syncthreads();
    if (c < 8) {
        float s = fcb[c];
        for (int k = 0; k < 128; ++k) s += sh[k * 8 + c];
        sh[1024 + c] = s;
    }
    __syncthreads();
    if (c == 0) {
        float mx = sh[1024];
#pragma unroll
        for (int j = 1; j < 8; ++j) mx = fmaxf(mx, sh[1024 + j]);
        float se = 0.f;
#pragma unroll
        for (int j = 0; j < 8; ++j) se += __expf(sh[1024 + j] - mx);
        float lse = logf(se) + mx;
#pragma unroll
        for (int j = 0; j < 8; ++j) out[g * 8 + j] = sh[1024 + j] - lse;
    }
}

// ---------------- launch --------------------------------------------------------
extern "C" void kernel_launch(void* const* d_in, const int* in_sizes, int n_in,
                              void* d_out, int out_size) {
    const float* x        = (const float*)d_in[0];
    const int*   ei       = (const int*)d_in[1];
    const int*   batch    = (const int*)d_in[2];
    const float* W1       = (const float*)d_in[3];
    const float* att_src1 = (const float*)d_in[4];
    const float* att_dst1 = (const float*)d_in[5];
    const float* b1       = (const float*)d_in[6];
    const float* W2       = (const float*)d_in[7];
    const float* att_src2 = (const float*)d_in[8];
    const float* att_dst2 = (const float*)d_in[9];
    const float* b2       = (const float*)d_in[10];
    const float* fcW      = (const float*)d_in[11];
    const float* fcb      = (const float*)d_in[12];
    float*       out      = (float*)d_out;

    const int GB = (N_NODES + 63) / 64;
    const int FB = (E4 + N_NODES + 255) / 256;

    zero_deg_kernel<<<(N_NODES + 255) / 256, 256>>>();
    hist_kernel<<<(E4 + 255) / 256, 256>>>(ei);
    scan_kernel<<<1, 1024>>>();
    gemm_att_kernel<<<GB, 256>>>(x, W1, att_src1, att_dst1, 1, N_NODES);
    fill_kernel<<<FB, 256>>>(ei);
    agg_kernel<<<(N_NODES + 7) / 8, 256>>>(b1);

    gemm_att_kernel<<<GB, 256>>>(nullptr, W2, att_src2, att_dst2, 0, N_NODES);
    agg_kernel<<<(N_NODES + 7) / 8, 256>>>(nullptr);

    zero_pool_kernel<<<(NGRAPH * HC + 255) / 256, 256>>>();
    pool_kernel<<<(N_NODES + 127) / 128, 128>>>(batch);
    final_kernel<<<NGRAPH, 128>>>(fcW, fcb, b2, out);
}